// round 17
// baseline (speedup 1.0000x reference)
#include <cuda_runtime.h>
#include <cuda_bf16.h>
#include <math.h>

#define NN 20000
#define EE 640000
#define HH 128
#define NB 16
#define SCAN_BLOCKS 79   // ceil(NN/256)

// ---------------- scratch ----------------
__device__ int   g_src[EE];
__device__ int   g_dst[EE];
__device__ float g_e[(size_t)NN * 128];
__device__ float g_q[(size_t)NN * 128];
__device__ float g_k[(size_t)NN * 128];
__device__ float g_ev[(size_t)NN * 3];
__device__ int g_counts[NN];                 // 0 at prep entry; scan resets
__device__ int g_excl[NN];
__device__ int g_bsum[128];
__device__ int g_offs[NN + 1];
__device__ int g_cursor[NN];
__device__ unsigned g_pk[EE];                // src | (bin<<20), CSR-ordered by dst
__device__ unsigned short g_pdst[EE];        // dst per CSR position
__device__ float g_ex[EE];                   // exp(logit) per CSR position

// packed bf16 hi/lo pair tables (uint2 = {hi_pair, lo_pair}, pair = 2 adjacent cols)
__device__ uint2 g_xpk[(size_t)NN * 64];
__device__ uint2 g_tpk[(size_t)NN * 64];
__device__ uint2 g_epk[(size_t)NN * 64];
__device__ uint2 g_w1t[128 * 128];           // [col][j], j=0..127 (K=256)
__device__ uint2 g_w2t[128 * 64];
__device__ uint2 g_wqt[128 * 64];
__device__ uint2 g_wkt[128 * 64];

// ---------------- helpers ----------------
__device__ __forceinline__ void split2(float f0, float f1, unsigned& hi, unsigned& lo) {
    __nv_bfloat162 h = __floats2bfloat162_rn(f0, f1);
    float r0 = f0 - __bfloat162float(h.x);
    float r1 = f1 - __bfloat162float(h.y);
    __nv_bfloat162 l = __floats2bfloat162_rn(r0, r1);
    hi = *reinterpret_cast<unsigned*>(&h);
    lo = *reinterpret_cast<unsigned*>(&l);
}
__device__ __forceinline__ void mma16(float* c, unsigned a0, unsigned a1, unsigned a2, unsigned a3,
                                      unsigned b0, unsigned b1) {
    asm volatile(
        "mma.sync.aligned.m16n8k16.row.col.f32.bf16.bf16.f32 "
        "{%0,%1,%2,%3},{%4,%5,%6,%7},{%8,%9},{%0,%1,%2,%3};"
        : "+f"(c[0]), "+f"(c[1]), "+f"(c[2]), "+f"(c[3])
        : "r"(a0), "r"(a1), "r"(a2), "r"(a3), "r"(b0), "r"(b1));
}
// inclusive scan over the block; all 32 lanes of warp 0 run the second-level shfl.
template<int NT>
__device__ __forceinline__ int block_incl_scan(int v, int tid) {
    __shared__ int wsum[NT / 32];
    int lane = tid & 31, wid = tid >> 5;
    int x = v;
    #pragma unroll
    for (int off = 1; off < 32; off <<= 1) {
        int y = __shfl_up_sync(~0u, x, off);
        if (lane >= off) x += y;
    }
    if (lane == 31) wsum[wid] = x;
    __syncthreads();
    if (wid == 0) {
        int ws = (lane < NT / 32) ? wsum[lane] : 0;
        #pragma unroll
        for (int off = 1; off < NT / 32; off <<= 1) {
            int y = __shfl_up_sync(~0u, ws, off);
            if (lane >= off) ws += y;
        }
        if (lane < NT / 32) wsum[lane] = ws;
    }
    __syncthreads();
    return x + (wid ? wsum[wid - 1] : 0);
}

// ---------------- prep: dtype-detect + normalize + histogram + ev (i<NN) ----------------
__global__ void prep_kernel(const int* __restrict__ ei_raw, const float* __restrict__ pos) {
    __shared__ int s_is64;
    if (threadIdx.x == 0) {
        int allzero = 1;
        #pragma unroll
        for (int i = 1; i < 128; i += 2)
            if (ei_raw[i] != 0) allzero = 0;
        s_is64 = allzero;
    }
    __syncthreads();
    int i = blockIdx.x * blockDim.x + threadIdx.x;
    if (i >= EE) return;
    int s, d;
    if (s_is64) {
        const long long* e = (const long long*)ei_raw;
        s = (int)e[i];
        d = (int)e[(size_t)EE + i];
    } else {
        s = ei_raw[i];
        d = ei_raw[EE + i];
    }
    g_src[i] = s;
    g_dst[i] = d;
    atomicAdd(&g_counts[d], 1);
    if (i < NN) {
        float vx = pos[d * 3 + 0] - pos[s * 3 + 0];
        float vy = pos[d * 3 + 1] - pos[s * 3 + 1];
        float vz = pos[d * 3 + 2] - pos[s * 3 + 2];
        float inv = 1.0f / (sqrtf(vx * vx + vy * vy + vz * vz) + 1e-8f);
        g_ev[i * 3 + 0] = vx * inv;
        g_ev[i * 3 + 1] = vy * inv;
        g_ev[i * 3 + 2] = vz * inv;
    }
}

// ---------------- two-level scan ----------------
__global__ void scan1_kernel() {
    int tid = threadIdx.x;
    int i = blockIdx.x * 256 + tid;
    int v = (i < NN) ? g_counts[i] : 0;
    if (i < NN) g_counts[i] = 0;             // restore invariant
    int incl = block_incl_scan<256>(v, tid);
    if (i < NN) g_excl[i] = incl - v;
    if (tid == 255) g_bsum[blockIdx.x] = incl;
}
__global__ void scan2_kernel() {
    int tid = threadIdx.x;                   // 128 threads
    int v = (tid < SCAN_BLOCKS) ? g_bsum[tid] : 0;
    int incl = block_incl_scan<128>(v, tid);
    if (tid < SCAN_BLOCKS) g_bsum[tid] = incl - v;   // exclusive prefix
    if (tid == 127) g_offs[NN] = incl;               // grand total (= EE)
}
__global__ void scan3_kernel() {
    int i = blockIdx.x * 256 + threadIdx.x;
    if (i >= NN) return;
    int o = g_bsum[blockIdx.x] + g_excl[i];
    g_offs[i] = o;
    g_cursor[i] = o;
}

// ---------------- scatter: CSR order, pack src + angle bin, store dst ----------------
__global__ void scatter_edges_kernel() {
    int i = blockIdx.x * blockDim.x + threadIdx.x;
    if (i >= EE) return;
    int s = g_src[i];
    int d = g_dst[i];
    float c = g_ev[d * 3 + 0] * g_ev[s * 3 + 0]
            + g_ev[d * 3 + 1] * g_ev[s * 3 + 1]
            + g_ev[d * 3 + 2] * g_ev[s * 3 + 2];
    c = fminf(fmaxf(c, -1.f), 1.f);
    int cnt = 0;
    #pragma unroll
    for (int t = 0; t < 17; t++) cnt += ((-1.f + 0.125f * (float)t) < c) ? 1 : 0;
    int b = min(max(cnt - 1, 0), NB - 1);
    int p = atomicAdd(&g_cursor[d], 1);
    g_pk[p] = (unsigned)s | ((unsigned)b << 20);
    g_pdst[p] = (unsigned short)d;
}

// ---------------- packers ----------------
__global__ void pack_x_kernel(const float* __restrict__ x) {
    int idx = blockIdx.x * blockDim.x + threadIdx.x;
    if (idx >= NN * 64) return;
    float2 v = ((const float2*)x)[idx];
    unsigned h, l;
    split2(v.x, v.y, h, l);
    g_xpk[idx] = make_uint2(h, l);
}

__global__ void pack_w_kernel(const float* __restrict__ W1, const float* __restrict__ W2,
                              const float* __restrict__ Wq, const float* __restrict__ Wk) {
    int y = blockIdx.y;
    const float* W = (y == 0) ? W1 : (y == 1) ? W2 : (y == 2) ? Wq : Wk;
    uint2* Wt = (y == 0) ? g_w1t : (y == 1) ? g_w2t : (y == 2) ? g_wqt : g_wkt;
    int jmax = (y == 0) ? 128 : 64;
    int idx = blockIdx.x * blockDim.x + threadIdx.x;
    if (idx >= 128 * jmax) return;
    int col = idx / jmax, j = idx % jmax;
    float w0 = W[(size_t)(2 * j) * 128 + col];
    float w1 = W[(size_t)(2 * j + 1) * 128 + col];
    unsigned h, l;
    split2(w0, w1, h, l);
    Wt[col * jmax + j] = make_uint2(h, l);
}

// ================= packed bf16 GEMM =================
template<int K, int GATHER, int ACT, int WPK, int WF32>
__device__ __forceinline__ void gemm_pk_body(
    const uint2* __restrict__ Apk, const uint2* __restrict__ Wt,
    const float* __restrict__ bias, float* __restrict__ C,
    uint2* __restrict__ Cpk, int M)
{
    __shared__ __align__(16) uint2 Bs[2][128][20];
    int tid = threadIdx.x, lane = tid & 31, wid = tid >> 5;
    int gid = lane >> 2, tig = lane & 3;
    int warpRow = (wid & 3) * 32;
    int warpCol = (wid >> 2) * 64;
    int rowBase = blockIdx.x * 128;
    const int NT = K / 32;
    const int AJ = GATHER ? 64 : (K / 2);

    const uint2* ap[4];
    const uint2* ap2[4];
    #pragma unroll
    for (int i = 0; i < 4; i++) {
        int gr = rowBase + warpRow + i * 8 + gid;
        int row = (gr < M) ? gr : 0;
        if (GATHER) {
            ap[i]  = Apk + (size_t)g_src[row] * 64;
            ap2[i] = Apk + (size_t)g_dst[row] * 64;
        } else {
            ap[i] = Apk + (size_t)row * AJ;
        }
    }

    float acc[2][8][4];
    #pragma unroll
    for (int m = 0; m < 2; m++)
        #pragma unroll
        for (int n = 0; n < 8; n++)
            #pragma unroll
            for (int j = 0; j < 4; j++) acc[m][n][j] = 0.f;

    #pragma unroll
    for (int rr = 0; rr < 8; rr++) {
        int idx = tid + rr * 256;
        int col = idx >> 4, j = idx & 15;
        Bs[0][col][j] = Wt[(size_t)col * (K / 2) + j];
    }
    __syncthreads();

    #pragma unroll
    for (int t = 0; t < NT; t++) {
        if (t + 1 < NT) {
            #pragma unroll
            for (int rr = 0; rr < 8; rr++) {
                int idx = tid + rr * 256;
                int col = idx >> 4, j = idx & 15;
                Bs[(t + 1) & 1][col][j] = Wt[(size_t)col * (K / 2) + (t + 1) * 16 + j];
            }
        }
        const uint2* ab[4];
        int jt;
        if (GATHER) {
            bool first = t < NT / 2;
            #pragma unroll
            for (int i = 0; i < 4; i++) ab[i] = first ? ap[i] : ap2[i];
            jt = (first ? t : t - NT / 2) * 16;
        } else {
            #pragma unroll
            for (int i = 0; i < 4; i++) ab[i] = ap[i];
            jt = t * 16;
        }

        #pragma unroll
        for (int s = 0; s < 2; s++) {
            int ja = jt + s * 8;
            uint2 A0[4], A1[4];
            #pragma unroll
            for (int i = 0; i < 4; i++) {
                A0[i] = ab[i][ja + tig];
                A1[i] = ab[i][ja + tig + 4];
            }
            #pragma unroll
            for (int n = 0; n < 8; n++) {
                int col = warpCol + n * 8 + gid;
                uint2 b0 = Bs[t & 1][col][s * 8 + tig];
                uint2 b1 = Bs[t & 1][col][s * 8 + tig + 4];
                #pragma unroll
                for (int m = 0; m < 2; m++) {
                    mma16(acc[m][n], A0[2*m].x, A0[2*m+1].x, A1[2*m].x, A1[2*m+1].x, b0.x, b1.x);
                    mma16(acc[m][n], A0[2*m].x, A0[2*m+1].x, A1[2*m].x, A1[2*m+1].x, b0.y, b1.y);
                    mma16(acc[m][n], A0[2*m].y, A0[2*m+1].y, A1[2*m].y, A1[2*m+1].y, b0.x, b1.x);
                }
            }
        }
        __syncthreads();
    }

    #pragma unroll
    for (int m = 0; m < 2; m++) {
        int r0 = rowBase + warpRow + m * 16 + gid;
        int r1 = r0 + 8;
        #pragma unroll
        for (int n = 0; n < 8; n++) {
            int col = warpCol + n * 8 + tig * 2;
            float bz0 = bias[col], bz1 = bias[col + 1];
            float v0 = acc[m][n][0] + bz0, v1 = acc[m][n][1] + bz1;
            float v2 = acc[m][n][2] + bz0, v3 = acc[m][n][3] + bz1;
            if (ACT) {
                v0 = v0 / (1.f + expf(-v0)); v1 = v1 / (1.f + expf(-v1));
                v2 = v2 / (1.f + expf(-v2)); v3 = v3 / (1.f + expf(-v3));
            }
            int jout = (warpCol >> 1) + n * 4 + tig;
            if (r0 < M) {
                if (WF32) *(float2*)(C + (size_t)r0 * 128 + col) = make_float2(v0, v1);
                if (WPK) { unsigned h, l; split2(v0, v1, h, l); Cpk[(size_t)r0 * 64 + jout] = make_uint2(h, l); }
            }
            if (r1 < M) {
                if (WF32) *(float2*)(C + (size_t)r1 * 128 + col) = make_float2(v2, v3);
                if (WPK) { unsigned h, l; split2(v2, v3, h, l); Cpk[(size_t)r1 * 64 + jout] = make_uint2(h, l); }
            }
        }
    }
}

__global__ __launch_bounds__(256, 2) void gemm1_kernel(
    const float* __restrict__ b1, int M) {
    gemm_pk_body<256, 1, 1, 1, 0>(g_xpk, g_w1t, b1, nullptr, g_tpk, M);
}
__global__ __launch_bounds__(256, 2) void gemm2_kernel(
    const float* __restrict__ b2, float* __restrict__ e, int M) {
    gemm_pk_body<128, 0, 0, 1, 1>(g_tpk, g_w2t, b2, e, g_epk, M);
}
__global__ __launch_bounds__(256, 2) void gemm_qk_kernel(
    const float* __restrict__ bq, float* __restrict__ q,
    const float* __restrict__ bk, float* __restrict__ k, int M) {
    if (blockIdx.y == 0) gemm_pk_body<128, 0, 0, 0, 1>(g_epk, g_wqt, bq, q, nullptr, M);
    else                 gemm_pk_body<128, 0, 0, 0, 1>(g_epk, g_wkt, bk, k, nullptr, M);
}

// ---------------- pass 1: edge-parallel logits (quarter-warp per CSR position) ----------
__global__ __launch_bounds__(256) void logit_kernel() {
    int gw = (blockIdx.x * blockDim.x + threadIdx.x) >> 5;   // global warp
    int lane = threadIdx.x & 31;
    int sub = lane >> 3, sl = lane & 7;
    int pos = gw * 4 + sub;
    if (pos >= EE) return;

    unsigned pk = g_pk[pos];
    int s = pk & 0xFFFFF;
    int d = g_pdst[pos];

    const float4* kr = (const float4*)g_k + (size_t)s * 32;
    const float4* qr = (const float4*)g_q + (size_t)d * 32;

    float acc = 0.f;
    #pragma unroll
    for (int i = 0; i < 4; i++) {
        float4 a = qr[sl + 8 * i];
        float4 b = kr[sl + 8 * i];
        acc += a.x * b.x + a.y * b.y + a.z * b.z + a.w * b.w;
    }
    #pragma unroll
    for (int off = 4; off; off >>= 1) acc += __shfl_xor_sync(~0u, acc, off, 8);
    if (sl == 0) g_ex[pos] = expf(acc * 0.08838834764831843f);   // 1/sqrt(128)
}

// ---------------- pass 2: warp-per-node accumulate, depth-2 rotating pipeline ----------
#define ACC_CASE(B) case B: a##B.x += ex*ev.x; a##B.y += ex*ev.y; \
                            a##B.z += ex*ev.z; a##B.w += ex*ev.w; sb##B += ex; break;

__global__ __launch_bounds__(256, 2) void accum_kernel(float* __restrict__ out)
{
    int gw = (blockIdx.x * blockDim.x + threadIdx.x) >> 5;
    int lane = threadIdx.x & 31;
    if (gw >= NN) return;
    int n = gw;

    const float4* e4 = (const float4*)g_e;

    float4 z = make_float4(0.f, 0.f, 0.f, 0.f);
    float4 a0=z,a1=z,a2=z,a3=z,a4=z,a5=z,a6=z,a7=z,
           a8=z,a9=z,a10=z,a11=z,a12=z,a13=z,a14=z,a15=z;
    float sb0=0,sb1=0,sb2=0,sb3=0,sb4=0,sb5=0,sb6=0,sb7=0,
          sb8=0,sb9=0,sb10=0,sb11=0,sb12=0,sb13=0,sb14=0,sb15=0;

    int pos = g_offs[n];
    int end = g_offs[n + 1];

    // rotating 2-slot pipeline: ev gather issued 2 iterations before use
    unsigned pk0 = 0, pk1 = 0;
    float ex0 = 0.f, ex1 = 0.f;
    float4 ev0 = z, ev1 = z;
    if (pos < end) {
        pk0 = g_pk[pos]; ex0 = g_ex[pos];
        ev0 = e4[(size_t)(pk0 & 0xFFFFF) * 32 + lane];
    }
    if (pos + 1 < end) {
        pk1 = g_pk[pos + 1]; ex1 = g_ex[pos + 1];
        ev1 = e4[(size_t)(pk1 & 0xFFFFF) * 32 + lane];
    }

    for (; pos < end; pos++) {
        unsigned cpk = pk0; float cex = ex0; float4 cev = ev0;
        pk0 = pk1; ex0 = ex1; ev0 = ev1;
        if (pos + 2 < end) {
            unsigned np = g_pk[pos + 2];
            pk1 = np; ex1 = g_ex[pos + 2];
            ev1 = e4[(size_t)(np & 0xFFFFF) * 32 + lane];
        }
        {
            float ex = cex; float4 ev = cev;
            switch (cpk >> 20) {
                ACC_CASE(0)  ACC_CASE(1)  ACC_CASE(2)  ACC_CASE(3)
                ACC_CASE(4)  ACC_CASE(5)  ACC_CASE(6)  ACC_CASE(7)
                ACC_CASE(8)  ACC_CASE(9)  ACC_CASE(10) ACC_CASE(11)
                ACC_CASE(12) ACC_CASE(13) ACC_CASE(14) ACC_CASE(15)
            }
        }
    }

    float i0  = 1.f/(sb0 +1e-16f), i1  = 1.f/(sb1 +1e-16f), i2  = 1.f/(sb2 +1e-16f), i3  = 1.f/(sb3 +1e-16f);
    float i4  = 1.f/(sb4 +1e-16f), i5  = 1.f/(sb5 +1e-16f), i6  = 1.f/(sb6 +1e-16f), i7  = 1.f/(sb7 +1e-16f);
    float i8  = 1.f/(sb8 +1e-16f), i9  = 1.f/(sb9 +1e-16f), i10 = 1.f/(sb10+1e-16f), i11 = 1.f/(sb11+1e-16f);
    float i12 = 1.f/(sb12+1e-16f), i13 = 1.f/(sb13+1e-16f), i14 = 1.f/(sb14+1e-16f), i15 = 1.f/(sb15+1e-16f);

    float4* op = (float4*)(out + (size_t)n * (HH * NB) + (size_t)lane * 4 * NB);
    op[0]  = make_float4(a0.x*i0,  a1.x*i1,  a2.x*i2,  a3.x*i3);
    op[1]  = make_float4(a4.x*i4,  a5.x*i5,  a6.x*i6,  a7.x*i7);
    op[2]  = make_float4(a8.x*i8,  a9.x*i9,  a10.x*i10, a11.x*i11);
    op[3]  = make_float4(a12.x*i12, a13.x*i13, a14.x*i14, a15.x*i15);
    op[4]  = make_float4(a0.y*i0,  a1.y*i1,  a2.y*i2,  a3.y*i3);
    op[5]  = make_float4(a4.y*i4,  a5.y*i5,  a6.y*i6,  a7.y*i7);
    op[6]  = make_float4(a8.y*i8,  a9.y*i9,  a10.y*i10, a11.y*i11);
    op[7]  = make_float4(a12.y*i12, a13.y*i13, a14.y*i14, a15.y*i15);
    op[8]  = make_float4(a0.z*i0,  a1.z*i1,  a2.z*i2,  a3.z*i3);
    op[9]  = make_float4(a4.z*i4,  a5.z*i5,  a6.z*i6,  a7.z*i7);
    op[10] = make_float4(a8.z*i8,  a9.z*i9,  a10.z*i10, a11.z*i11);
    op[11] = make_float4(a12.z*i12, a13.z*i13, a14.z*i14, a15.z*i15);
    op[12] = make_float4(a0.w*i0,  a1.w*i1,  a2.w*i2,  a3.w*i3);
    op[13] = make_float4(a4.w*i4,  a5.w*i5,  a6.w*i6,  a7.w*i7);
    op[14] = make_float4(a8.w*i8,  a9.w*i9,  a10.w*i10, a11.w*i11);
    op[15] = make_float4(a12.w*i12, a13.w*i13, a14.w*i14, a15.w*i15);
}

// ---------------- launcher: fork-join overlap of CSR chain vs pack+GEMM chain ----------
extern "C" void kernel_launch(void* const* d_in, const int* in_sizes, int n_in,
                              void* d_out, int out_size) {
    const float* x   = (const float*)d_in[0];
    const float* pos = (const float*)d_in[1];
    const int*   ei  = (const int*)d_in[2];
    const float* W1  = (const float*)d_in[3];
    const float* b1  = (const float*)d_in[4];
    const float* W2  = (const float*)d_in[5];
    const float* b2  = (const float*)d_in[6];
    const float* Wq  = (const float*)d_in[7];
    const float* bq  = (const float*)d_in[8];
    const float* Wk  = (const float*)d_in[9];
    const float* bk  = (const float*)d_in[10];
    float* out = (float*)d_out;

    float *pe, *pq, *pk;
    cudaGetSymbolAddress((void**)&pe, g_e);
    cudaGetSymbolAddress((void**)&pq, g_q);
    cudaGetSymbolAddress((void**)&pk, g_k);

    cudaStream_t s2;
    cudaStreamCreateWithFlags(&s2, cudaStreamNonBlocking);
    cudaEvent_t evFork, evPack, evPrep, evScat;
    cudaEventCreateWithFlags(&evFork, cudaEventDisableTiming);
    cudaEventCreateWithFlags(&evPack, cudaEventDisableTiming);
    cudaEventCreateWithFlags(&evPrep, cudaEventDisableTiming);
    cudaEventCreateWithFlags(&evScat, cudaEventDisableTiming);

    // fork side stream off the main (capture) stream
    cudaEventRecord(evFork, 0);
    cudaStreamWaitEvent(s2, evFork, 0);

    // side stream: packs (independent of indices)
    pack_x_kernel<<<(NN * 64 + 255) / 256, 256, 0, s2>>>(x);
    dim3 wgrid(64, 4);
    pack_w_kernel<<<wgrid, 256, 0, s2>>>(W1, W2, Wq, Wk);
    cudaEventRecord(evPack, s2);

    // main stream: prep (indices + ev)
    prep_kernel<<<(EE + 255) / 256, 256>>>(ei, pos);
    cudaEventRecord(evPrep, 0);

    // side stream: CSR chain after prep (two-level scan + scatter)
    cudaStreamWaitEvent(s2, evPrep, 0);
    scan1_kernel<<<SCAN_BLOCKS, 256, 0, s2>>>();
    scan2_kernel<<<1, 128, 0, s2>>>();
    scan3_kernel<<<SCAN_BLOCKS, 256, 0, s2>>>();
    scatter_edges_kernel<<<(EE + 255) / 256, 256, 0, s2>>>();
    cudaEventRecord(evScat, s2);

    // main stream: GEMM chain (needs packs + prep's src/dst)
    cudaStreamWaitEvent(0, evPack, 0);
    int gblocks = (NN + 127) / 128;
    gemm1_kernel<<<gblocks, 256>>>(b1, NN);
    gemm2_kernel<<<gblocks, 256>>>(b2, pe, NN);
    dim3 qkgrid(gblocks, 2);
    gemm_qk_kernel<<<qkgrid, 256>>>(bq, pq, bk, pk, NN);

    // join: logit/accum need scatter's CSR + q/k
    cudaStreamWaitEvent(0, evScat, 0);
    logit_kernel<<<(EE / 4 * 32 + 255) / 256, 256>>>();
    accum_kernel<<<(NN * 32 + 255) / 256, 256>>>(out);
}